// round 6
// baseline (speedup 1.0000x reference)
#include <cuda_runtime.h>
#include <cuda_bf16.h>

#define B_TOTAL        65536
#define N_K            64
#define ROW_FLOATS     (N_K * 3)          // 192 floats per row per tensor
#define DEGREE         3
#define SAMPLES        20
#define ROWS_PER_BLOCK 16
#define THREADS        (ROWS_PER_BLOCK * SAMPLES)  // 320
#define NBLOCKS        (B_TOTAL / ROWS_PER_BLOCK)  // 4096
#define KF_STRIDE      69   // 4 zeros + 64 knots + 1 pad; 69 mod 32 = 5 (odd -> bank permutation)
#define C_STRIDE       65   // 64 coeffs + 1 pad;          65 mod 32 = 1 (odd -> bank permutation)

__device__ double        g_sum;     // zero-init; reset by last block each run
__device__ unsigned int  g_count;   // zero-init; reset by last block each run

// De Boor sample. kf padded: kf[i]=0 for i<4, knots[i-4] else. i0 = s-3.
__device__ __forceinline__ void deboor_eval(const float* __restrict__ kf,
                                            const float* __restrict__ cx,
                                            const float* __restrict__ cy,
                                            float t, int i0,
                                            float& ox, float& oy)
{
    float kfv[7];
#pragma unroll
    for (int m = 1; m < 7; m++) kfv[m] = kf[i0 + m];   // kfv[0] never used

    float px[4], py[4];
#pragma unroll
    for (int k = 0; k < 4; k++) {
        px[k] = cx[i0 + k];
        py[k] = cy[i0 + k];
    }

#pragma unroll
    for (int l = 1; l <= DEGREE; l++) {
#pragma unroll
        for (int k = 3; k >= 1; k--) {
            if (k < l) break;
            float ki = kfv[k];
            float kj = kfv[k + 4 - l];
            float denom = kj - ki;
            float alpha = (denom != 0.0f) ? __fdividef(t - ki, denom) : 0.0f;
            px[k] = fmaf(alpha, px[k] - px[k - 1], px[k - 1]);
            py[k] = fmaf(alpha, py[k] - py[k - 1], py[k - 1]);
        }
    }
    ox = px[3];   // homogeneous weight stays exactly 1 -> no division
    oy = py[3];
}

// Interleaved branchless searches: count of knots <= t for two rows at once,
// so the two dependent LDS chains overlap. knots live at kf[4..67].
__device__ __forceinline__ void dual_knot_search(const float* __restrict__ ka, float ta,
                                                 const float* __restrict__ kb, float tb,
                                                 int& i0a, int& i0b)
{
    int a = 0, b = 0;
#pragma unroll
    for (int step = 32; step > 0; step >>= 1) {
        int ca = a + step;
        int cb = b + step;
        if (ca <= 60 && ka[ca + 3] <= ta) a = ca;
        if (cb <= 60 && kb[cb + 3] <= tb) b = cb;
    }
    i0a = a;
    i0b = b;
}

__global__ __launch_bounds__(THREADS)
void bspline_loss_fused(const float* __restrict__ pred,
                        const float* __restrict__ tru,
                        float* __restrict__ out)
{
    __shared__ float s_kf[2][ROWS_PER_BLOCK][KF_STRIDE];
    __shared__ float s_cx[2][ROWS_PER_BLOCK][C_STRIDE];
    __shared__ float s_cy[2][ROWS_PER_BLOCK][C_STRIDE];

    // Zero kf padding: 2 tensors x 16 rows x 4 slots = 128 scalars.
    if (threadIdx.x < 2 * ROWS_PER_BLOCK * 4) {
        int tsel = threadIdx.x >> 6;
        int r    = (threadIdx.x >> 2) & 15;
        int z    = threadIdx.x & 3;
        s_kf[tsel][r][z] = 0.0f;
    }

    // Transpose: item = 4 triples = 3 coalesced LDG.128 + 12 scalar STS.
    // items = 2 tensors x 16 rows x 16 groups = 512.
    {
        const size_t base = (size_t)blockIdx.x * ROWS_PER_BLOCK * ROW_FLOATS;
        const float4* gp = reinterpret_cast<const float4*>(pred + base);
        const float4* gt = reinterpret_cast<const float4*>(tru + base);
        const int G = 2 * ROWS_PER_BLOCK * 16;
#pragma unroll
        for (int id = threadIdx.x; id < G; id += THREADS) {
            const int g    = id & 15;
            const int r    = (id >> 4) & 15;
            const int tsel = id >> 8;
            const float4* src = tsel ? gt : gp;
            const int idx4 = 48 * r + 3 * g;
            float4 v0 = src[idx4 + 0];   // k0 x0 y0 k1
            float4 v1 = src[idx4 + 1];   // x1 y1 k2 x2
            float4 v2 = src[idx4 + 2];   // y2 k3 x3 y3
            const int i = 4 * g;
            s_kf[tsel][r][4 + i + 0] = v0.x;
            s_kf[tsel][r][4 + i + 1] = v0.w;
            s_kf[tsel][r][4 + i + 2] = v1.z;
            s_kf[tsel][r][4 + i + 3] = v2.y;
            s_cx[tsel][r][i + 0] = v0.y;
            s_cx[tsel][r][i + 1] = v1.x;
            s_cx[tsel][r][i + 2] = v1.w;
            s_cx[tsel][r][i + 3] = v2.z;
            s_cy[tsel][r][i + 0] = v0.z;
            s_cy[tsel][r][i + 1] = v1.y;
            s_cy[tsel][r][i + 2] = v2.x;
            s_cy[tsel][r][i + 3] = v2.w;
        }
    }
    __syncthreads();

    // Lane-fast row mapping: adjacent lanes -> different rows, same sample j.
    const int row = threadIdx.x & 15;
    const int j   = threadIdx.x >> 4;

    const float* kp  = &s_kf[0][row][0];
    const float* kt  = &s_kf[1][row][0];
    const float* cpx = &s_cx[0][row][0];
    const float* ctx = &s_cx[1][row][0];
    const float* cpy = &s_cy[0][row][0];
    const float* cty = &s_cy[1][row][0];

    const float hp = kp[64];                   // high = knots[60] = kf[64], low = 0
    const float ht = kt[64];
    const float frac = (float)j / 19.0f;
    const float tp = frac * hp;
    const float tt = frac * ht;

    int i0p, i0t;
    dual_knot_search(kp, tp, kt, tt, i0p, i0t);

    float pxv, pyv, txv, tyv;
    deboor_eval(kp, cpx, cpy, tp, i0p, pxv, pyv);
    deboor_eval(kt, ctx, cty, tt, i0t, txv, tyv);

    float dx = pxv - txv;
    float dy = pyv - tyv;
    float val = fmaf(dx, dx, dy * dy);

    // Warp reduce (10 full warps).
#pragma unroll
    for (int o = 16; o > 0; o >>= 1)
        val += __shfl_down_sync(0xFFFFFFFFu, val, o);

    __shared__ float warpsum[THREADS / 32];
    const int wid  = threadIdx.x >> 5;
    const int lane = threadIdx.x & 31;
    if (lane == 0) warpsum[wid] = val;
    __syncthreads();

    if (threadIdx.x == 0) {
        double tot = 0.0;
#pragma unroll
        for (int w = 0; w < THREADS / 32; w++) tot += (double)warpsum[w];
        atomicAdd(&g_sum, tot);
        __threadfence();
        unsigned int ticket = atomicAdd(&g_count, 1u);
        if (ticket == NBLOCKS - 1) {
            out[0] = (float)(g_sum / (double)((long long)B_TOTAL * SAMPLES));
            g_sum = 0.0;
            __threadfence();
            g_count = 0u;
        }
    }
}

extern "C" void kernel_launch(void* const* d_in, const int* in_sizes, int n_in,
                              void* d_out, int out_size)
{
    const float* pred = (const float*)d_in[0];
    const float* tru  = (const float*)d_in[1];
    float* out = (float*)d_out;

    bspline_loss_fused<<<NBLOCKS, THREADS>>>(pred, tru, out);
}